// round 1
// baseline (speedup 1.0000x reference)
#include <cuda_runtime.h>
#include <math.h>

#define MDIM 4096
#define B1 0.9f
#define B2 0.999f
#define EPSV 1e-8f
#define LRV 0.1f
#define NSTEPS 199

// Scratch (allocation-free rule: __device__ globals)
__device__ float d_Qs[(size_t)MDIM * MDIM];   // 64 MB symmetrized matrix
__device__ float d_w[2][MDIM];
__device__ float d_mt[MDIM];
__device__ float d_vt[MDIM];

// ---------------------------------------------------------------------------
// Qs = 0.5*(va + va^T), tiled transpose to keep both reads coalesced.
// ---------------------------------------------------------------------------
__global__ void prep_qs_kernel(const float* __restrict__ va) {
    __shared__ float tile[32][33];
    int bx = blockIdx.x * 32;
    int by = blockIdx.y * 32;
    int tx = threadIdx.x, ty = threadIdx.y;
    // load the transposed block coalesced: va[bx+ty][by+tx]
    tile[ty][tx] = va[(size_t)(bx + ty) * MDIM + (by + tx)];
    __syncthreads();
    // coalesced read of va[by+ty][bx+tx], add transpose element from tile
    size_t idx = (size_t)(by + ty) * MDIM + (bx + tx);
    d_Qs[idx] = 0.5f * (va[idx] + tile[tx][ty]);
}

// ---------------------------------------------------------------------------
// Init: w = 1, mt = vt = 0
// ---------------------------------------------------------------------------
__global__ void init_state_kernel() {
    int i = blockIdx.x * blockDim.x + threadIdx.x;
    if (i < MDIM) {
        d_w[0][i] = 1.0f;
        d_mt[i] = 0.0f;
        d_vt[i] = 0.0f;
    }
}

// ---------------------------------------------------------------------------
// One Adam step: g = Qs @ (w_in - mean); elementwise Adam; write w_out.
// One warp per row; x staged in shared memory once per block.
// ---------------------------------------------------------------------------
#define STEP_THREADS 256
#define WARPS_PER_BLOCK (STEP_THREADS / 32)

__global__ __launch_bounds__(STEP_THREADS)
void adam_step_kernel(const float* __restrict__ mean,
                      const float* __restrict__ w_in,
                      float* __restrict__ w_out,
                      float step_lr,          // LR / bc1
                      float inv_sqrt_bc2)     // 1 / sqrt(bc2)
{
    __shared__ float xs[MDIM];  // 16 KB: x = w_in - mean
    int tid = threadIdx.x;
    #pragma unroll
    for (int j = tid; j < MDIM; j += STEP_THREADS)
        xs[j] = w_in[j] - mean[j];
    __syncthreads();

    int warp = tid >> 5;
    int lane = tid & 31;
    int row  = blockIdx.x * WARPS_PER_BLOCK + warp;

    const float4* __restrict__ q = reinterpret_cast<const float4*>(
        d_Qs + (size_t)row * MDIM);
    const float4* __restrict__ xv4 = reinterpret_cast<const float4*>(xs);

    float acc = 0.0f;
    // 4096 floats = 1024 float4; 32 lanes -> 32 iterations per lane
    #pragma unroll 8
    for (int it = lane; it < MDIM / 4; it += 32) {
        float4 qv = q[it];
        float4 xv = xv4[it];
        acc = fmaf(qv.x, xv.x, acc);
        acc = fmaf(qv.y, xv.y, acc);
        acc = fmaf(qv.z, xv.z, acc);
        acc = fmaf(qv.w, xv.w, acc);
    }
    // warp reduction
    #pragma unroll
    for (int off = 16; off > 0; off >>= 1)
        acc += __shfl_xor_sync(0xFFFFFFFFu, acc, off);

    if (lane == 0) {
        float g  = acc;
        float mt = B1 * d_mt[row] + (1.0f - B1) * g;
        float vt = B2 * d_vt[row] + (1.0f - B2) * g * g;
        d_mt[row] = mt;
        d_vt[row] = vt;
        float denom = sqrtf(vt) * inv_sqrt_bc2 + EPSV;
        w_out[row] = w_in[row] - step_lr * mt / denom;
    }
}

// ---------------------------------------------------------------------------
// kernel_launch: prep Qs, init state, 199 step kernels (graph-capturable).
// Inputs per metadata order: mean [4096], va [4096*4096], xt [unused].
// ---------------------------------------------------------------------------
extern "C" void kernel_launch(void* const* d_in, const int* in_sizes, int n_in,
                              void* d_out, int out_size) {
    const float* mean = (const float*)d_in[0];
    const float* va   = (const float*)d_in[1];
    float* out = (float*)d_out;

    (void)in_sizes; (void)n_in; (void)out_size;

    float* w_buf0;  cudaGetSymbolAddress((void**)&w_buf0, d_w);
    float* w_buf1 = w_buf0 + MDIM;

    // 1) symmetrize
    dim3 tb(32, 32);
    dim3 tg(MDIM / 32, MDIM / 32);
    prep_qs_kernel<<<tg, tb>>>(va);

    // 2) init state
    init_state_kernel<<<(MDIM + 255) / 256, 256>>>();

    // 3) 199 Adam steps; double-buffer w; last step writes d_out.
    int grid = MDIM / WARPS_PER_BLOCK;  // 512 blocks
    for (int t = 1; t <= NSTEPS; ++t) {
        double bc1 = 1.0 - pow((double)B1, (double)t);
        double bc2 = 1.0 - pow((double)B2, (double)t);
        float step_lr      = (float)((double)LRV / bc1);
        float inv_sqrt_bc2 = (float)(1.0 / sqrt(bc2));

        const float* w_in = ((t - 1) & 1) ? w_buf1 : w_buf0;
        float* w_out;
        if (t == NSTEPS)      w_out = out;
        else if (t & 1)       w_out = w_buf1;
        else                  w_out = w_buf0;

        adam_step_kernel<<<grid, STEP_THREADS>>>(mean, w_in, w_out,
                                                 step_lr, inv_sqrt_bc2);
    }
}